// round 13
// baseline (speedup 1.0000x reference)
#include <cuda_runtime.h>
#include <cuda_bf16.h>
#include <cstdint>

#define BATCH 65536

// SMEM byte offsets (phi kernel)
#define SM_AHI  0            // 64 rows x 132 words = 33792 B
#define SM_ALO  33792
#define SM_WB   67584        // two weight chunk buffers, 65536 B each
#define SM_BIAS 198656       // b2[256] b5[256] w6[256] b6[1]
#define SM_QBUF 201744       // 64 x 4 fp32
#define SMEM_BYTES 202768

// weight fragment images, LDS.128-friendly layout:
// per chunk: hi[8192 u32] then lo[8192 u32];
// hi word addr = ((ksx*4 + warpN)*32 + lane)*16 + ntl*2 + reg
__device__ uint32_t g_wf[2u * 9u * 2u * 8192u];
// pair-input images: [pair 3][tile 1024][hl 2][2048] u32 (64 rows x 32 words)
__device__ uint32_t g_ainp[3u * 1024u * 2u * 2048u];

// ---------------------------------------------------------------------------
__device__ __forceinline__ uint32_t smem_u32(const void* p) {
    uint32_t a;
    asm("{ .reg .u64 t; cvta.to.shared.u64 t, %1; cvt.u32.u64 %0, t; }" : "=r"(a) : "l"(p));
    return a;
}
__device__ __forceinline__ void cp16(uint32_t saddr, const void* g) {
    asm volatile("cp.async.cg.shared.global [%0], [%1], 16;" :: "r"(saddr), "l"(g));
}
#define CP_COMMIT() asm volatile("cp.async.commit_group;" ::: "memory")
#define CP_WAIT(n)  asm volatile("cp.async.wait_group %0;" :: "n"(n) : "memory")

__device__ __forceinline__ void split2(float a, float b, uint32_t& hi, uint32_t& lo) {
    __nv_bfloat16 h0 = __float2bfloat16_rn(a), h1 = __float2bfloat16_rn(b);
    float l0 = a - __bfloat162float(h0), l1 = b - __bfloat162float(h1);
    __nv_bfloat162 hh = __halves2bfloat162(h0, h1);
    __nv_bfloat162 ll = __halves2bfloat162(__float2bfloat16_rn(l0), __float2bfloat16_rn(l1));
    hi = *(uint32_t*)&hh; lo = *(uint32_t*)&ll;
}

__device__ __forceinline__ void mma_bf16(float (&d)[4], const uint32_t (&a)[4],
                                         const uint32_t b0, const uint32_t b1) {
    asm("mma.sync.aligned.m16n8k16.row.col.f32.bf16.bf16.f32 "
        "{%0,%1,%2,%3},{%4,%5,%6,%7},{%8,%9},{%0,%1,%2,%3};"
        : "+f"(d[0]), "+f"(d[1]), "+f"(d[2]), "+f"(d[3])
        : "r"(a[0]), "r"(a[1]), "r"(a[2]), "r"(a[3]), "r"(b0), "r"(b1));
}

// ---------------------------------------------------------------------------
// Build pair-input bf16 hi/lo images. SMEM-staged for coalesced global writes.
// Block = 256 samples = 4 tiles. col 54 = 1.0 activates W1's bias row.
// ---------------------------------------------------------------------------
__global__ void build_ainp(const float* __restrict__ obs, const float* __restrict__ ag,
                           const float* __restrict__ gg,  const float* __restrict__ anch,
                           const float* __restrict__ act)
{
    extern __shared__ uint32_t sbuf[];          // [2][256 * 33] words, stride 33
    const int tid = threadIdx.x;
    int b = blockIdx.x * 256 + tid;
    int T0 = blockIdx.x * 4;

    const float* ob  = obs  + (size_t)b * 55;
    const float* an  = anch + (size_t)b * 9;
    const float* agp = ag   + (size_t)b * 9;
    const float* gp  = gg   + (size_t)b * 9;
    const float* ac  = act  + (size_t)b * 4;
    const int o1s[3] = {0, 0, 1}, o2s[3] = {1, 2, 2};
    const int js[3]  = {3, 4, 6}, ks[3]  = {5, 7, 8};

    float row[64];
    for (int p = 0; p < 3; ++p) {
        bool sel = (an[js[p]] - an[ks[p]]) >= 0.0f;
        int bit2 = sel ? js[p] : ks[p];
        int oi = sel ? o1s[p] : o2s[p];
        int oj = sel ? o2s[p] : o1s[p];
        row[0] = agp[p]; row[1] = agp[bit2];
        row[2] = gp[p];  row[3] = gp[bit2];
#pragma unroll
        for (int c = 0; c < 10; ++c) row[4 + c] = ob[c];
        row[14] = (oi == 0) ? 1.f : 0.f;
        row[15] = (oi == 1) ? 1.f : 0.f;
        row[16] = (oi == 2) ? 1.f : 0.f;
        const float* of = ob + 10 + 15 * oi;
#pragma unroll
        for (int c = 0; c < 15; ++c) row[17 + c] = of[c];
        row[32] = (oj == 0) ? 1.f : 0.f;
        row[33] = (oj == 1) ? 1.f : 0.f;
        row[34] = (oj == 2) ? 1.f : 0.f;
        const float* os = ob + 10 + 15 * oj;
#pragma unroll
        for (int c = 0; c < 15; ++c) row[35 + c] = os[c];
#pragma unroll
        for (int c = 0; c < 4; ++c) row[50 + c] = ac[c];
        row[54] = 1.0f;
#pragma unroll
        for (int c = 55; c < 64; ++c) row[c] = 0.f;

        __syncthreads();   // previous pair's copy-out done
        uint32_t* sH = sbuf + (size_t)tid * 33;
        uint32_t* sL = sbuf + 256 * 33 + (size_t)tid * 33;
#pragma unroll
        for (int i = 0; i < 32; ++i) {
            uint32_t hi, lo;
            split2(row[2 * i], row[2 * i + 1], hi, lo);
            sH[i] = hi; sL[i] = lo;
        }
        __syncthreads();

        // coalesced copy-out: 16384 words -> g_ainp[p][T0..T0+3][hl][2048]
#pragma unroll
        for (int i = 0; i < 64; ++i) {
            int f = tid + i * 256;
            int h = f >> 13, r = f & 8191;
            int t = r >> 11, m = (r & 2047) >> 5, w = r & 31;
            uint32_t v = sbuf[h * (256 * 33) + (t * 64 + m) * 33 + w];
            g_ainp[(size_t)((p * 1024 + T0 + t) * 2 + h) * 2048 + (r & 2047)] = v;
        }
    }
}

// ---------------------------------------------------------------------------
// Pack weights (+bias row) into LDS.128-friendly per-lane B-fragment images
// ---------------------------------------------------------------------------
__global__ void prep_w(const float* __restrict__ w1, const float* __restrict__ b1,
                       const float* __restrict__ w2, const float* __restrict__ w5,
                       const float* __restrict__ w3, const float* __restrict__ b3,
                       const float* __restrict__ w4, const float* __restrict__ w7)
{
    int gid = blockIdx.x * 256 + threadIdx.x;          // 73728
    int lane = gid & 31, nt = (gid >> 5) & 31, ksx = (gid >> 10) & 3;
    int mc = gid >> 12, chunk = mc % 9, mlp = mc / 9;

    const float* W; const float* Bb = nullptr; int k0 = 0, Kmax = 256;
    if (mlp == 0) {
        if (chunk == 0)     { W = w1; Bb = b1; Kmax = 54; }
        else if (chunk < 5) { W = w2; k0 = (chunk - 1) * 64; }
        else                { W = w5; k0 = (chunk - 5) * 64; }
    } else {
        if (chunk == 0)     { W = w3; Bb = b3; Kmax = 54; }
        else if (chunk < 5) { W = w4; k0 = (chunk - 1) * 64; }
        else                { W = w7; k0 = (chunk - 5) * 64; }
    }

    int n = nt * 8 + (lane >> 2);
    int wN = nt >> 3, ntl = nt & 7;
    size_t cb = (size_t)(mlp * 9 + chunk) * 16384;
    size_t baseH = cb + (size_t)(((ksx * 4 + wN) * 32 + lane) * 16 + ntl * 2);
    size_t baseL = baseH + 8192;
#pragma unroll
    for (int j = 0; j < 2; ++j) {
        int k = k0 + ksx * 16 + (lane & 3) * 2 + j * 8;
        float v0 = 0.f, v1 = 0.f;
        if (k < Kmax)               v0 = W[(size_t)k * 256 + n];
        else if (Bb && k == 54)     v0 = Bb[n];
        if (k + 1 < Kmax)           v1 = W[(size_t)(k + 1) * 256 + n];
        else if (Bb && k + 1 == 54) v1 = Bb[n];
        uint32_t hi, lo;
        split2(v0, v1, hi, lo);
        g_wf[baseH + j] = hi;
        g_wf[baseL + j] = lo;
    }
}

// ---------------------------------------------------------------------------
// Chunk-stream pipelined GEMM (bf16 x3 split), ONE sync per chunk.
// Order per iteration: CP_WAIT(0) -> sync -> issue prefetch(k+1) -> compute.
// Safety: buffer (k+1)&1 was last READ during chunk k-1; the top sync orders
// all warps past that read AND makes chunk k + A-image writes visible.
// Global chunk sequence: seq[k] = k%5 for k<15, k-10 for k>=15.
// ---------------------------------------------------------------------------
__device__ __forceinline__ int seq_chunk(int k) { return (k < 15) ? (k % 5) : (k - 10); }

__device__ __forceinline__ void zero_acc(float (&acc)[2][8][4]) {
#pragma unroll
    for (int mt = 0; mt < 2; ++mt)
#pragma unroll
        for (int nt = 0; nt < 8; ++nt)
#pragma unroll
            for (int i = 0; i < 4; ++i) acc[mt][nt][i] = 0.f;
}

__device__ __forceinline__ void stage_issue(uint32_t sb, int buf, int gchunk, int tid) {
    uint32_t dst = sb + SM_WB + buf * 65536 + tid * 16;
    const uint4* src = (const uint4*)g_wf + (size_t)gchunk * 4096 + tid;
#pragma unroll
    for (int i = 0; i < 16; ++i)
        cp16(dst + i * 4096, src + i * 256);
    CP_COMMIT();
}

__device__ __forceinline__ void do_gemm(char* sm, uint32_t sb, int wbase, int nchunks,
                                        int& k, float (&acc)[2][8][4],
                                        int tid, int lane, int warpM, int warpN)
{
    const int l4 = lane >> 2, lm = lane & 3;
    const uint32_t* AH = (const uint32_t*)(sm + SM_AHI);
    const uint32_t* AL = (const uint32_t*)(sm + SM_ALO);

    for (int ci = 0; ci < nchunks; ++ci, ++k) {
        CP_WAIT(0);        // chunk k resident (only outstanding group)
        __syncthreads();   // + all warps done with chunk k-1 reads / A writes visible
        if (k + 1 < 19)
            stage_issue(sb, (k + 1) & 1, wbase + seq_chunk(k + 1), tid);

        const uint32_t* wb = (const uint32_t*)(sm + SM_WB + (k & 1) * 65536);
        const int akw = ci * 32;
#pragma unroll
        for (int ksx = 0; ksx < 4; ++ksx) {
            uint32_t ah[2][4], al[2][4];
#pragma unroll
            for (int mt = 0; mt < 2; ++mt) {
                int w0 = (warpM * 32 + mt * 16 + l4) * 132 + akw + ksx * 8 + lm;
                ah[mt][0] = AH[w0];        ah[mt][1] = AH[w0 + 8 * 132];
                ah[mt][2] = AH[w0 + 4];    ah[mt][3] = AH[w0 + 8 * 132 + 4];
                al[mt][0] = AL[w0];        al[mt][1] = AL[w0 + 8 * 132];
                al[mt][2] = AL[w0 + 4];    al[mt][3] = AL[w0 + 8 * 132 + 4];
            }
            // B hi fragments: 16 contiguous u32 per lane -> 4x LDS.128
            const uint4* bp = (const uint4*)wb + (size_t)(((ksx * 4 + warpN) * 32 + lane) * 4);
            uint4 h0 = bp[0], h1 = bp[1], h2 = bp[2], h3 = bp[3];
            uint32_t bh[8][2] = {
                {h0.x, h0.y}, {h0.z, h0.w}, {h1.x, h1.y}, {h1.z, h1.w},
                {h2.x, h2.y}, {h2.z, h2.w}, {h3.x, h3.y}, {h3.z, h3.w}};
#pragma unroll
            for (int nt = 0; nt < 8; ++nt) {
                mma_bf16(acc[0][nt], ah[0], bh[nt][0], bh[nt][1]);
                mma_bf16(acc[1][nt], ah[1], bh[nt][0], bh[nt][1]);
            }
#pragma unroll
            for (int nt = 0; nt < 8; ++nt) {
                mma_bf16(acc[0][nt], al[0], bh[nt][0], bh[nt][1]);
                mma_bf16(acc[1][nt], al[1], bh[nt][0], bh[nt][1]);
            }
            // B lo fragments
            const uint4* blp = bp + 2048;
            uint4 g0 = blp[0], g1 = blp[1], g2 = blp[2], g3 = blp[3];
            uint32_t bl[8][2] = {
                {g0.x, g0.y}, {g0.z, g0.w}, {g1.x, g1.y}, {g1.z, g1.w},
                {g2.x, g2.y}, {g2.z, g2.w}, {g3.x, g3.y}, {g3.z, g3.w}};
#pragma unroll
            for (int nt = 0; nt < 8; ++nt) {
                mma_bf16(acc[0][nt], ah[0], bl[nt][0], bl[nt][1]);
                mma_bf16(acc[1][nt], ah[1], bl[nt][0], bl[nt][1]);
            }
        }
    }
    __syncthreads();   // all warps done reading A images / WB before caller mutates
}

// ---------------------------------------------------------------------------
// Fused phi + rho: one CTA = 64 batch rows x one MLP. Grid 2048 x 256 thr.
// ---------------------------------------------------------------------------
__global__ void __launch_bounds__(256, 1)
phi_kernel(const float* __restrict__ B2a, const float* __restrict__ B5a,
           const float* __restrict__ W6a, const float* __restrict__ B6a,
           const float* __restrict__ B2b, const float* __restrict__ B5b,
           const float* __restrict__ W6b, const float* __restrict__ B6b,
           float* __restrict__ outp)
{
    extern __shared__ char sm[];
    const uint32_t sb = smem_u32(sm);
    const int tid = threadIdx.x, lane = tid & 31, wid = tid >> 5;
    const int warpM = wid & 1, warpN = wid >> 1;
    const int bx = blockIdx.x, mlp = bx >> 10, tile = bx & 1023;
    const int m0 = tile * 64;
    const int l4 = lane >> 2, lm = lane & 3;

    const float* B2 = mlp ? B2b : B2a;
    const float* B5 = mlp ? B5b : B5a;
    const float* W6 = mlp ? W6b : W6a;
    const float* B6 = mlp ? B6b : B6a;

    float* bias = (float*)(sm + SM_BIAS);
    float* qb   = (float*)(sm + SM_QBUF);

    const int wbase = mlp * 9;
    int k = 0;
    // prefetch chunk 0 immediately; overlaps bias + A-image staging below
    stage_issue(sb, 0, wbase + 0, tid);

    bias[tid] = B2[tid]; bias[256 + tid] = B5[tid]; bias[512 + tid] = W6[tid];
    if (tid == 0) bias[768] = B6[0];

    float acc[2][8][4];
    float sreg[2][8][4];
#pragma unroll
    for (int mt = 0; mt < 2; ++mt)
#pragma unroll
        for (int nt = 0; nt < 8; ++nt)
#pragma unroll
            for (int i = 0; i < 4; ++i) sreg[mt][nt][i] = 0.f;

    for (int p = 0; p < 3; ++p) {
        // stage pair-input images (hi/lo) into A buffers, row stride 132 words
#pragma unroll
        for (int hl = 0; hl < 2; ++hl) {
            const uint4* src = (const uint4*)(g_ainp + (size_t)((p * 1024 + tile) * 2 + hl) * 2048);
            char* dbase = sm + (hl ? SM_ALO : SM_AHI);
#pragma unroll
            for (int i = 0; i < 2; ++i) {
                int w4 = tid + i * 256;
                int row = w4 >> 3, cw4 = w4 & 7;
                *(uint4*)(dbase + (row * 132 + cw4 * 4) * 4) = src[w4];
            }
        }

        // ---- layer 1: acc = inp @ W1 (+b1 via bias row) ----
        zero_acc(acc);
        do_gemm(sm, sb, wbase, 1, k, acc, tid, lane, warpM, warpN);

        // epilogue 1: h = relu(acc) -> split -> A images
#pragma unroll
        for (int mt = 0; mt < 2; ++mt) {
            int r0 = warpM * 32 + mt * 16 + l4;
#pragma unroll
            for (int nt = 0; nt < 8; ++nt) {
                int cw = warpN * 32 + nt * 4 + lm;
                uint32_t hi, lo;
                split2(fmaxf(acc[mt][nt][0], 0.f), fmaxf(acc[mt][nt][1], 0.f), hi, lo);
                *(uint32_t*)(sm + SM_AHI + (r0 * 132 + cw) * 4) = hi;
                *(uint32_t*)(sm + SM_ALO + (r0 * 132 + cw) * 4) = lo;
                split2(fmaxf(acc[mt][nt][2], 0.f), fmaxf(acc[mt][nt][3], 0.f), hi, lo);
                *(uint32_t*)(sm + SM_AHI + ((r0 + 8) * 132 + cw) * 4) = hi;
                *(uint32_t*)(sm + SM_ALO + ((r0 + 8) * 132 + cw) * 4) = lo;
            }
        }

        // ---- layer 2: acc = h @ W2 ----
        zero_acc(acc);
        do_gemm(sm, sb, wbase, 4, k, acc, tid, lane, warpM, warpN);

        // epilogue 2 (registers): sreg += relu(acc + b2)
#pragma unroll
        for (int mt = 0; mt < 2; ++mt)
#pragma unroll
            for (int nt = 0; nt < 8; ++nt) {
                int col = warpN * 64 + nt * 8 + lm * 2;
                sreg[mt][nt][0] += fmaxf(acc[mt][nt][0] + bias[col], 0.f);
                sreg[mt][nt][1] += fmaxf(acc[mt][nt][1] + bias[col + 1], 0.f);
                sreg[mt][nt][2] += fmaxf(acc[mt][nt][2] + bias[col], 0.f);
                sreg[mt][nt][3] += fmaxf(acc[mt][nt][3] + bias[col + 1], 0.f);
            }
    }

    // s (register fragments) -> split A images
#pragma unroll
    for (int mt = 0; mt < 2; ++mt) {
        int r0 = warpM * 32 + mt * 16 + l4;
#pragma unroll
        for (int nt = 0; nt < 8; ++nt) {
            int cw = warpN * 32 + nt * 4 + lm;
            uint32_t hi, lo;
            split2(sreg[mt][nt][0], sreg[mt][nt][1], hi, lo);
            *(uint32_t*)(sm + SM_AHI + (r0 * 132 + cw) * 4) = hi;
            *(uint32_t*)(sm + SM_ALO + (r0 * 132 + cw) * 4) = lo;
            split2(sreg[mt][nt][2], sreg[mt][nt][3], hi, lo);
            *(uint32_t*)(sm + SM_AHI + ((r0 + 8) * 132 + cw) * 4) = hi;
            *(uint32_t*)(sm + SM_ALO + ((r0 + 8) * 132 + cw) * 4) = lo;
        }
    }

    // ---- rho: acc = s @ W5 ----
    zero_acc(acc);
    do_gemm(sm, sb, wbase, 4, k, acc, tid, lane, warpM, warpN);

    // rho epilogue: q = relu(acc + b5) . w6, reduce
#pragma unroll
    for (int mt = 0; mt < 2; ++mt) {
        float s0 = 0.f, s1 = 0.f;
#pragma unroll
        for (int nt = 0; nt < 8; ++nt) {
            int col = warpN * 64 + nt * 8 + lm * 2;
            float b5c0 = bias[256 + col], b5c1 = bias[256 + col + 1];
            float w6c0 = bias[512 + col], w6c1 = bias[512 + col + 1];
            s0 += fmaxf(acc[mt][nt][0] + b5c0, 0.f) * w6c0
                + fmaxf(acc[mt][nt][1] + b5c1, 0.f) * w6c1;
            s1 += fmaxf(acc[mt][nt][2] + b5c0, 0.f) * w6c0
                + fmaxf(acc[mt][nt][3] + b5c1, 0.f) * w6c1;
        }
        s0 += __shfl_xor_sync(0xffffffffu, s0, 1);
        s0 += __shfl_xor_sync(0xffffffffu, s0, 2);
        s1 += __shfl_xor_sync(0xffffffffu, s1, 1);
        s1 += __shfl_xor_sync(0xffffffffu, s1, 2);
        if (lm == 0) {
            int r0 = warpM * 32 + mt * 16 + l4;
            qb[r0 * 4 + warpN] = s0;
            qb[(r0 + 8) * 4 + warpN] = s1;
        }
    }
    __syncthreads();
    if (tid < 64)
        outp[(size_t)mlp * BATCH + m0 + tid] =
            qb[tid * 4] + qb[tid * 4 + 1] + qb[tid * 4 + 2] + qb[tid * 4 + 3] + bias[768];
}

// ---------------------------------------------------------------------------
extern "C" void kernel_launch(void* const* d_in, const int* in_sizes, int n_in,
                              void* d_out, int out_size)
{
    const float* obs    = (const float*)d_in[0];
    const float* ag     = (const float*)d_in[1];
    const float* gg     = (const float*)d_in[2];
    const float* anchor = (const float*)d_in[3];
    const float* act    = (const float*)d_in[4];
    const float* w1 = (const float*)d_in[5];  const float* b1 = (const float*)d_in[6];
    const float* w2 = (const float*)d_in[7];  const float* b2 = (const float*)d_in[8];
    const float* w3 = (const float*)d_in[9];  const float* b3 = (const float*)d_in[10];
    const float* w4 = (const float*)d_in[11]; const float* b4 = (const float*)d_in[12];
    const float* w5 = (const float*)d_in[13]; const float* b5 = (const float*)d_in[14];
    const float* w6 = (const float*)d_in[15]; const float* b6 = (const float*)d_in[16];
    const float* w7 = (const float*)d_in[17]; const float* b7 = (const float*)d_in[18];
    const float* w8 = (const float*)d_in[19]; const float* b8 = (const float*)d_in[20];
    float* out = (float*)d_out;

    cudaFuncSetAttribute(phi_kernel, cudaFuncAttributeMaxDynamicSharedMemorySize, SMEM_BYTES);
    cudaFuncSetAttribute(build_ainp, cudaFuncAttributeMaxDynamicSharedMemorySize, 67584);

    build_ainp<<<BATCH / 256, 256, 67584>>>(obs, ag, gg, anchor, act);
    prep_w<<<288, 256>>>(w1, b1, w2, w5, w3, b3, w4, w7);
    phi_kernel<<<2048, 256, SMEM_BYTES>>>(b2, b5, w6, b6, b4, b7, w8, b8, out);
}

// round 14
// speedup vs baseline: 1.3571x; 1.3571x over previous
#include <cuda_runtime.h>
#include <cuda_bf16.h>
#include <cstdint>

#define BATCH 65536

// SMEM byte offsets (phi kernel)
#define SM_AHI  0            // 64 rows x 132 words = 33792 B
#define SM_ALO  33792
#define SM_WB   67584        // two weight chunk buffers, 65536 B each
#define SM_BIAS 198656       // b2[256] b5[256] w6[256] b6[1]
#define SM_QBUF 201744       // 64 x 4 fp32
#define SMEM_BYTES 202768

// weight fragment images: [mlp 2][chunk 9][hl 2][ks 4][nt 32][lane 32][2] u32
__device__ uint32_t g_wf[2u * 9u * 2u * 8192u];
// pair-input images: [pair 3][tile 1024][hl 2][2048] u32 (64 rows x 32 words)
__device__ uint32_t g_ainp[3u * 1024u * 2u * 2048u];

// ---------------------------------------------------------------------------
__device__ __forceinline__ uint32_t smem_u32(const void* p) {
    uint32_t a;
    asm("{ .reg .u64 t; cvta.to.shared.u64 t, %1; cvt.u32.u64 %0, t; }" : "=r"(a) : "l"(p));
    return a;
}
__device__ __forceinline__ void cp16(uint32_t saddr, const void* g) {
    asm volatile("cp.async.cg.shared.global [%0], [%1], 16;" :: "r"(saddr), "l"(g));
}
#define CP_COMMIT() asm volatile("cp.async.commit_group;" ::: "memory")
#define CP_WAIT(n)  asm volatile("cp.async.wait_group %0;" :: "n"(n) : "memory")

__device__ __forceinline__ void split2(float a, float b, uint32_t& hi, uint32_t& lo) {
    __nv_bfloat16 h0 = __float2bfloat16_rn(a), h1 = __float2bfloat16_rn(b);
    float l0 = a - __bfloat162float(h0), l1 = b - __bfloat162float(h1);
    __nv_bfloat162 hh = __halves2bfloat162(h0, h1);
    __nv_bfloat162 ll = __halves2bfloat162(__float2bfloat16_rn(l0), __float2bfloat16_rn(l1));
    hi = *(uint32_t*)&hh; lo = *(uint32_t*)&ll;
}

__device__ __forceinline__ void mma_bf16(float (&d)[4], const uint32_t (&a)[4],
                                         const uint32_t (&b)[2]) {
    asm("mma.sync.aligned.m16n8k16.row.col.f32.bf16.bf16.f32 "
        "{%0,%1,%2,%3},{%4,%5,%6,%7},{%8,%9},{%0,%1,%2,%3};"
        : "+f"(d[0]), "+f"(d[1]), "+f"(d[2]), "+f"(d[3])
        : "r"(a[0]), "r"(a[1]), "r"(a[2]), "r"(a[3]), "r"(b[0]), "r"(b[1]));
}

// ---------------------------------------------------------------------------
// Fused prep kernel.
//   Blocks [0, 256):   build pair-input bf16 hi/lo images (smem-staged).
//   Blocks [256, 544): pack weights (+bias row) into B-fragment hi/lo images.
// The two halves are independent; both complete before phi_kernel launches.
// ---------------------------------------------------------------------------
__global__ void prep_all(const float* __restrict__ obs, const float* __restrict__ ag,
                         const float* __restrict__ gg,  const float* __restrict__ anch,
                         const float* __restrict__ act,
                         const float* __restrict__ w1, const float* __restrict__ b1,
                         const float* __restrict__ w2, const float* __restrict__ w5,
                         const float* __restrict__ w3, const float* __restrict__ b3,
                         const float* __restrict__ w4, const float* __restrict__ w7)
{
    extern __shared__ uint32_t sbuf[];          // [2][256 * 33] words, stride 33
    const int tid = threadIdx.x;

    if (blockIdx.x >= 256) {
        // ---- weight packing path (identical math/layout to R10 prep_w) ----
        int gid = (blockIdx.x - 256) * 256 + tid;          // 73728
        int lane = gid & 31, nt = (gid >> 5) & 31, ksx = (gid >> 10) & 3;
        int mc = gid >> 12, chunk = mc % 9, mlp = mc / 9;

        const float* W; const float* Bb = nullptr; int k0 = 0, Kmax = 256;
        if (mlp == 0) {
            if (chunk == 0)     { W = w1; Bb = b1; Kmax = 54; }
            else if (chunk < 5) { W = w2; k0 = (chunk - 1) * 64; }
            else                { W = w5; k0 = (chunk - 5) * 64; }
        } else {
            if (chunk == 0)     { W = w3; Bb = b3; Kmax = 54; }
            else if (chunk < 5) { W = w4; k0 = (chunk - 1) * 64; }
            else                { W = w7; k0 = (chunk - 5) * 64; }
        }

        int n = nt * 8 + (lane >> 2);
        size_t baseH = ((size_t)((mlp * 9 + chunk) * 2 + 0) * 4 + ksx) * 2048 + (size_t)nt * 64 + lane * 2;
        size_t baseL = ((size_t)((mlp * 9 + chunk) * 2 + 1) * 4 + ksx) * 2048 + (size_t)nt * 64 + lane * 2;
#pragma unroll
        for (int j = 0; j < 2; ++j) {
            int k = k0 + ksx * 16 + (lane & 3) * 2 + j * 8;
            float v0 = 0.f, v1 = 0.f;
            if (k < Kmax)               v0 = W[(size_t)k * 256 + n];
            else if (Bb && k == 54)     v0 = Bb[n];
            if (k + 1 < Kmax)           v1 = W[(size_t)(k + 1) * 256 + n];
            else if (Bb && k + 1 == 54) v1 = Bb[n];
            uint32_t hi, lo;
            split2(v0, v1, hi, lo);
            g_wf[baseH + j] = hi;
            g_wf[baseL + j] = lo;
        }
        return;
    }

    // ---- pair-input build path (identical math/layout to R10 build_ainp) ----
    int b = blockIdx.x * 256 + tid;
    int T0 = blockIdx.x * 4;

    const float* ob  = obs  + (size_t)b * 55;
    const float* an  = anch + (size_t)b * 9;
    const float* agp = ag   + (size_t)b * 9;
    const float* gp  = gg   + (size_t)b * 9;
    const float* ac  = act  + (size_t)b * 4;
    const int o1s[3] = {0, 0, 1}, o2s[3] = {1, 2, 2};
    const int js[3]  = {3, 4, 6}, ks[3]  = {5, 7, 8};

    float row[64];
    for (int p = 0; p < 3; ++p) {
        bool sel = (an[js[p]] - an[ks[p]]) >= 0.0f;
        int bit2 = sel ? js[p] : ks[p];
        int oi = sel ? o1s[p] : o2s[p];
        int oj = sel ? o2s[p] : o1s[p];
        row[0] = agp[p]; row[1] = agp[bit2];
        row[2] = gp[p];  row[3] = gp[bit2];
#pragma unroll
        for (int c = 0; c < 10; ++c) row[4 + c] = ob[c];
        row[14] = (oi == 0) ? 1.f : 0.f;
        row[15] = (oi == 1) ? 1.f : 0.f;
        row[16] = (oi == 2) ? 1.f : 0.f;
        const float* of = ob + 10 + 15 * oi;
#pragma unroll
        for (int c = 0; c < 15; ++c) row[17 + c] = of[c];
        row[32] = (oj == 0) ? 1.f : 0.f;
        row[33] = (oj == 1) ? 1.f : 0.f;
        row[34] = (oj == 2) ? 1.f : 0.f;
        const float* os = ob + 10 + 15 * oj;
#pragma unroll
        for (int c = 0; c < 15; ++c) row[35 + c] = os[c];
#pragma unroll
        for (int c = 0; c < 4; ++c) row[50 + c] = ac[c];
        row[54] = 1.0f;
#pragma unroll
        for (int c = 55; c < 64; ++c) row[c] = 0.f;

        __syncthreads();   // previous pair's copy-out done
        uint32_t* sH = sbuf + (size_t)tid * 33;
        uint32_t* sL = sbuf + 256 * 33 + (size_t)tid * 33;
#pragma unroll
        for (int i = 0; i < 32; ++i) {
            uint32_t hi, lo;
            split2(row[2 * i], row[2 * i + 1], hi, lo);
            sH[i] = hi; sL[i] = lo;
        }
        __syncthreads();

        // coalesced copy-out: 16384 words -> g_ainp[p][T0..T0+3][hl][2048]
#pragma unroll
        for (int i = 0; i < 64; ++i) {
            int f = tid + i * 256;
            int h = f >> 13, r = f & 8191;
            int t = r >> 11, m = (r & 2047) >> 5, w = r & 31;
            uint32_t v = sbuf[h * (256 * 33) + (t * 64 + m) * 33 + w];
            g_ainp[(size_t)((p * 1024 + T0 + t) * 2 + h) * 2048 + (r & 2047)] = v;
        }
    }
}

// ---------------------------------------------------------------------------
// Chunk-stream pipelined GEMM (R10 structure, unchanged).
// Global chunk sequence: seq[k] = k%5 for k<15, k-10 for k>=15.
// ---------------------------------------------------------------------------
__device__ __forceinline__ int seq_chunk(int k) { return (k < 15) ? (k % 5) : (k - 10); }

__device__ __forceinline__ void zero_acc(float (&acc)[2][8][4]) {
#pragma unroll
    for (int mt = 0; mt < 2; ++mt)
#pragma unroll
        for (int nt = 0; nt < 8; ++nt)
#pragma unroll
            for (int i = 0; i < 4; ++i) acc[mt][nt][i] = 0.f;
}

__device__ __forceinline__ void stage_issue(uint32_t sb, int buf, int gchunk, int tid) {
    uint32_t dst = sb + SM_WB + buf * 65536 + tid * 16;
    const uint4* src = (const uint4*)g_wf + (size_t)gchunk * 4096 + tid;
#pragma unroll
    for (int i = 0; i < 16; ++i)
        cp16(dst + i * 4096, src + i * 256);
    CP_COMMIT();
}

__device__ __forceinline__ void do_gemm(char* sm, uint32_t sb, int wbase, int nchunks,
                                        int& k, float (&acc)[2][8][4],
                                        int tid, int lane, int warpM, int warpN)
{
    const int l4 = lane >> 2, lm = lane & 3;
    const uint32_t* AH = (const uint32_t*)(sm + SM_AHI);
    const uint32_t* AL = (const uint32_t*)(sm + SM_ALO);

    for (int ci = 0; ci < nchunks; ++ci, ++k) {
        if (k + 1 < 19) {
            stage_issue(sb, (k + 1) & 1, wbase + seq_chunk(k + 1), tid);
            CP_WAIT(1);
        } else {
            CP_WAIT(0);
        }
        __syncthreads();   // chunk k resident for all warps; A images visible

        const uint32_t* wb = (const uint32_t*)(sm + SM_WB + (k & 1) * 65536);
        const int akw = ci * 32;
#pragma unroll
        for (int ksx = 0; ksx < 4; ++ksx) {
            uint32_t ah[2][4], al[2][4];
#pragma unroll
            for (int mt = 0; mt < 2; ++mt) {
                int w0 = (warpM * 32 + mt * 16 + l4) * 132 + akw + ksx * 8 + lm;
                ah[mt][0] = AH[w0];        ah[mt][1] = AH[w0 + 8 * 132];
                ah[mt][2] = AH[w0 + 4];    ah[mt][3] = AH[w0 + 8 * 132 + 4];
                al[mt][0] = AL[w0];        al[mt][1] = AL[w0 + 8 * 132];
                al[mt][2] = AL[w0 + 4];    al[mt][3] = AL[w0 + 8 * 132 + 4];
            }
            uint32_t b0[8][2];
#pragma unroll
            for (int nt = 0; nt < 8; ++nt) {
                int idx = (ksx * 32 + warpN * 8 + nt) * 64 + lane * 2;
                b0[nt][0] = wb[idx]; b0[nt][1] = wb[idx + 1];
            }
#pragma unroll
            for (int nt = 0; nt < 8; ++nt) {
                mma_bf16(acc[0][nt], ah[0], b0[nt]);
                mma_bf16(acc[1][nt], ah[1], b0[nt]);
            }
#pragma unroll
            for (int nt = 0; nt < 8; ++nt) {
                mma_bf16(acc[0][nt], al[0], b0[nt]);
                mma_bf16(acc[1][nt], al[1], b0[nt]);
            }
#pragma unroll
            for (int nt = 0; nt < 8; ++nt) {
                int idx = 8192 + (ksx * 32 + warpN * 8 + nt) * 64 + lane * 2;
                uint32_t bl[2] = { wb[idx], wb[idx + 1] };
                mma_bf16(acc[0][nt], ah[0], bl);
                mma_bf16(acc[1][nt], ah[1], bl);
            }
        }
        __syncthreads();   // compute done; buffer (k&1) free for reuse at k+2
    }
}

// ---------------------------------------------------------------------------
// Fused phi + rho: one CTA = 64 batch rows x one MLP. Grid 2048 x 256 thr.
// ---------------------------------------------------------------------------
__global__ void __launch_bounds__(256, 1)
phi_kernel(const float* __restrict__ B2a, const float* __restrict__ B5a,
           const float* __restrict__ W6a, const float* __restrict__ B6a,
           const float* __restrict__ B2b, const float* __restrict__ B5b,
           const float* __restrict__ W6b, const float* __restrict__ B6b,
           float* __restrict__ outp)
{
    extern __shared__ char sm[];
    const uint32_t sb = smem_u32(sm);
    const int tid = threadIdx.x, lane = tid & 31, wid = tid >> 5;
    const int warpM = wid & 1, warpN = wid >> 1;
    const int bx = blockIdx.x, mlp = bx >> 10, tile = bx & 1023;
    const int m0 = tile * 64;
    const int l4 = lane >> 2, lm = lane & 3;

    const float* B2 = mlp ? B2b : B2a;
    const float* B5 = mlp ? B5b : B5a;
    const float* W6 = mlp ? W6b : W6a;
    const float* B6 = mlp ? B6b : B6a;

    float* bias = (float*)(sm + SM_BIAS);
    float* qb   = (float*)(sm + SM_QBUF);

    const int wbase = mlp * 9;
    int k = 0;
    // prefetch chunk 0 immediately; overlaps bias + A-image staging below
    stage_issue(sb, 0, wbase + 0, tid);

    bias[tid] = B2[tid]; bias[256 + tid] = B5[tid]; bias[512 + tid] = W6[tid];
    if (tid == 0) bias[768] = B6[0];

    float acc[2][8][4];
    float sreg[2][8][4];
#pragma unroll
    for (int mt = 0; mt < 2; ++mt)
#pragma unroll
        for (int nt = 0; nt < 8; ++nt)
#pragma unroll
            for (int i = 0; i < 4; ++i) sreg[mt][nt][i] = 0.f;

    for (int p = 0; p < 3; ++p) {
        // stage pair-input images (hi/lo) into A buffers, row stride 132 words
#pragma unroll
        for (int hl = 0; hl < 2; ++hl) {
            const uint4* src = (const uint4*)(g_ainp + (size_t)((p * 1024 + tile) * 2 + hl) * 2048);
            char* dbase = sm + (hl ? SM_ALO : SM_AHI);
#pragma unroll
            for (int i = 0; i < 2; ++i) {
                int w4 = tid + i * 256;
                int row = w4 >> 3, cw4 = w4 & 7;
                *(uint4*)(dbase + (row * 132 + cw4 * 4) * 4) = src[w4];
            }
        }

        // ---- layer 1: acc = inp @ W1 (+b1 via bias row) ----
        zero_acc(acc);
        do_gemm(sm, sb, wbase, 1, k, acc, tid, lane, warpM, warpN);

        // epilogue 1: h = relu(acc) -> split -> A images
#pragma unroll
        for (int mt = 0; mt < 2; ++mt) {
            int r0 = warpM * 32 + mt * 16 + l4;
#pragma unroll
            for (int nt = 0; nt < 8; ++nt) {
                int cw = warpN * 32 + nt * 4 + lm;
                uint32_t hi, lo;
                split2(fmaxf(acc[mt][nt][0], 0.f), fmaxf(acc[mt][nt][1], 0.f), hi, lo);
                *(uint32_t*)(sm + SM_AHI + (r0 * 132 + cw) * 4) = hi;
                *(uint32_t*)(sm + SM_ALO + (r0 * 132 + cw) * 4) = lo;
                split2(fmaxf(acc[mt][nt][2], 0.f), fmaxf(acc[mt][nt][3], 0.f), hi, lo);
                *(uint32_t*)(sm + SM_AHI + ((r0 + 8) * 132 + cw) * 4) = hi;
                *(uint32_t*)(sm + SM_ALO + ((r0 + 8) * 132 + cw) * 4) = lo;
            }
        }

        // ---- layer 2: acc = h @ W2 ----
        zero_acc(acc);
        do_gemm(sm, sb, wbase, 4, k, acc, tid, lane, warpM, warpN);

        // epilogue 2 (registers): sreg += relu(acc + b2)
#pragma unroll
        for (int mt = 0; mt < 2; ++mt)
#pragma unroll
            for (int nt = 0; nt < 8; ++nt) {
                int col = warpN * 64 + nt * 8 + lm * 2;
                sreg[mt][nt][0] += fmaxf(acc[mt][nt][0] + bias[col], 0.f);
                sreg[mt][nt][1] += fmaxf(acc[mt][nt][1] + bias[col + 1], 0.f);
                sreg[mt][nt][2] += fmaxf(acc[mt][nt][2] + bias[col], 0.f);
                sreg[mt][nt][3] += fmaxf(acc[mt][nt][3] + bias[col + 1], 0.f);
            }
    }

    // s (register fragments) -> split A images
#pragma unroll
    for (int mt = 0; mt < 2; ++mt) {
        int r0 = warpM * 32 + mt * 16 + l4;
#pragma unroll
        for (int nt = 0; nt < 8; ++nt) {
            int cw = warpN * 32 + nt * 4 + lm;
            uint32_t hi, lo;
            split2(sreg[mt][nt][0], sreg[mt][nt][1], hi, lo);
            *(uint32_t*)(sm + SM_AHI + (r0 * 132 + cw) * 4) = hi;
            *(uint32_t*)(sm + SM_ALO + (r0 * 132 + cw) * 4) = lo;
            split2(sreg[mt][nt][2], sreg[mt][nt][3], hi, lo);
            *(uint32_t*)(sm + SM_AHI + ((r0 + 8) * 132 + cw) * 4) = hi;
            *(uint32_t*)(sm + SM_ALO + ((r0 + 8) * 132 + cw) * 4) = lo;
        }
    }

    // ---- rho: acc = s @ W5 ----
    zero_acc(acc);
    do_gemm(sm, sb, wbase, 4, k, acc, tid, lane, warpM, warpN);

    // rho epilogue: q = relu(acc + b5) . w6, reduce
#pragma unroll
    for (int mt = 0; mt < 2; ++mt) {
        float s0 = 0.f, s1 = 0.f;
#pragma unroll
        for (int nt = 0; nt < 8; ++nt) {
            int col = warpN * 64 + nt * 8 + lm * 2;
            float b5c0 = bias[256 + col], b5c1 = bias[256 + col + 1];
            float w6c0 = bias[512 + col], w6c1 = bias[512 + col + 1];
            s0 += fmaxf(acc[mt][nt][0] + b5c0, 0.f) * w6c0
                + fmaxf(acc[mt][nt][1] + b5c1, 0.f) * w6c1;
            s1 += fmaxf(acc[mt][nt][2] + b5c0, 0.f) * w6c0
                + fmaxf(acc[mt][nt][3] + b5c1, 0.f) * w6c1;
        }
        s0 += __shfl_xor_sync(0xffffffffu, s0, 1);
        s0 += __shfl_xor_sync(0xffffffffu, s0, 2);
        s1 += __shfl_xor_sync(0xffffffffu, s1, 1);
        s1 += __shfl_xor_sync(0xffffffffu, s1, 2);
        if (lm == 0) {
            int r0 = warpM * 32 + mt * 16 + l4;
            qb[r0 * 4 + warpN] = s0;
            qb[(r0 + 8) * 4 + warpN] = s1;
        }
    }
    __syncthreads();
    if (tid < 64)
        outp[(size_t)mlp * BATCH + m0 + tid] =
            qb[tid * 4] + qb[tid * 4 + 1] + qb[tid * 4 + 2] + qb[tid * 4 + 3] + bias[768];
}

// ---------------------------------------------------------------------------
extern "C" void kernel_launch(void* const* d_in, const int* in_sizes, int n_in,
                              void* d_out, int out_size)
{
    const float* obs    = (const float*)d_in[0];
    const float* ag     = (const float*)d_in[1];
    const float* gg     = (const float*)d_in[2];
    const float* anchor = (const float*)d_in[3];
    const float* act    = (const float*)d_in[4];
    const float* w1 = (const float*)d_in[5];  const float* b1 = (const float*)d_in[6];
    const float* w2 = (const float*)d_in[7];  const float* b2 = (const float*)d_in[8];
    const float* w3 = (const float*)d_in[9];  const float* b3 = (const float*)d_in[10];
    const float* w4 = (const float*)d_in[11]; const float* b4 = (const float*)d_in[12];
    const float* w5 = (const float*)d_in[13]; const float* b5 = (const float*)d_in[14];
    const float* w6 = (const float*)d_in[15]; const float* b6 = (const float*)d_in[16];
    const float* w7 = (const float*)d_in[17]; const float* b7 = (const float*)d_in[18];
    const float* w8 = (const float*)d_in[19]; const float* b8 = (const float*)d_in[20];
    float* out = (float*)d_out;

    cudaFuncSetAttribute(phi_kernel, cudaFuncAttributeMaxDynamicSharedMemorySize, SMEM_BYTES);
    cudaFuncSetAttribute(prep_all, cudaFuncAttributeMaxDynamicSharedMemorySize, 67584);

    prep_all<<<544, 256, 67584>>>(obs, ag, gg, anchor, act,
                                  w1, b1, w2, w5, w3, b3, w4, w7);
    phi_kernel<<<2048, 256, SMEM_BYTES>>>(b2, b5, w6, b6, b4, b7, w8, b8, out);
}